// round 14
// baseline (speedup 1.0000x reference)
#include <cuda_runtime.h>
#include <cuda_bf16.h>
#include <cstdint>

#define BATCH   16
#define CCH     512
#define NPIX    1024          // 32*32
#define HEADS   4
#define HD      128           // CCH / HEADS
#define GROUPS  32
#define CPG     (CCH / GROUPS)   // 16
#define GEPS    1e-5f
#define ATT_SCALE 0.088388347648318447f   // 128^-0.5
#define NBH     (BATCH * HEADS)           // 64

// ---------------- scratch (device globals; no allocations allowed) ----------
__device__ float g_att[BATCH * CCH * NPIX];                 // 33.5 MB fp32
__device__ float g_gnmu [BATCH * GROUPS];
__device__ float g_gninv[BATCH * GROUPS];
__device__ __nv_bfloat16 g_qc[(size_t)BATCH * CCH * NPIX];  // [b][c][q], scaled
__device__ __nv_bfloat16 g_kc[(size_t)BATCH * CCH * NPIX];  // [b][c][q]
__device__ __nv_bfloat16 g_vb[(size_t)BATCH * CCH * NPIX];  // [b][c][key]
__device__ __nv_bfloat16 g_qT[(size_t)NBH * NPIX * HD];     // [bh][q][c]
__device__ __nv_bfloat16 g_kT[(size_t)NBH * NPIX * HD];     // [bh][key][c]

__device__ __forceinline__ uint32_t pack_bf2(float a, float b) {
    __nv_bfloat162 h = __floats2bfloat162_rn(a, b);
    return *(uint32_t*)&h;
}
__device__ __forceinline__ uint32_t smaddr(const void* p) {
    return (uint32_t)__cvta_generic_to_shared(p);
}

// ---------------- GroupNorm stats only ---------------------------------------
__global__ void gn_stats(const float* __restrict__ x) {
    const int bg = blockIdx.x;
    const int b  = bg / GROUPS;
    const int g  = bg % GROUPS;
    const int M  = CPG * NPIX;                  // 16384
    const float* xp = x + ((size_t)b * CCH + (size_t)g * CPG) * NPIX;

    float s = 0.f, ss = 0.f;
    for (int i = threadIdx.x; i < M; i += blockDim.x) {
        float v = xp[i];
        s += v; ss += v * v;
    }
    __shared__ float red[64];
    #pragma unroll
    for (int o = 16; o; o >>= 1) {
        s  += __shfl_xor_sync(0xffffffffu, s,  o);
        ss += __shfl_xor_sync(0xffffffffu, ss, o);
    }
    const int warp = threadIdx.x >> 5, lane = threadIdx.x & 31;
    if (lane == 0) { red[warp] = s; red[warp + 32] = ss; }
    __syncthreads();
    if (threadIdx.x == 0) {
        float s2 = 0.f, ss2 = 0.f;
        #pragma unroll
        for (int i = 0; i < 8; i++) { s2 += red[i]; ss2 += red[i + 32]; }
        float mu  = s2 / (float)M;
        float var = ss2 / (float)M - mu * mu;
        g_gnmu[bg]  = mu;
        g_gninv[bg] = rsqrtf(var + GEPS);
    }
}

// ---------------- bf16 MMA GEMM (R8/R9-proven) --------------------------------
#define BM 128
#define BN 128
#define BK 32
#define SW 20

#define MMA_BF16(c, a, b) \
    asm volatile("mma.sync.aligned.m16n8k16.row.col.f32.bf16.bf16.f32 " \
        "{%0,%1,%2,%3},{%4,%5,%6,%7},{%8,%9},{%0,%1,%2,%3};" \
        : "+f"((c)[0]), "+f"((c)[1]), "+f"((c)[2]), "+f"((c)[3]) \
        : "r"((a)[0]), "r"((a)[1]), "r"((a)[2]), "r"((a)[3]), \
          "r"((b)[0]), "r"((b)[1]))

template<int MODE>
__global__ void __launch_bounds__(256, 2)
bf16_gemm(const float* __restrict__ Wg, const float* __restrict__ Xg,
          float* __restrict__ Cg,
          const float* __restrict__ bias, const float* __restrict__ res,
          const float* __restrict__ gamma, const float* __restrict__ beta,
          int M, int N, int K, int lda, int ldb) {
    const int z  = blockIdx.z;
    const int m0 = blockIdx.y * BM;
    const int n0 = blockIdx.x * BN;
    const size_t Boff = (size_t)z * CCH * NPIX;

    __shared__ uint32_t As[BM * SW];
    __shared__ uint32_t Bs[BN * SW];
    __shared__ float s_mu[GROUPS], s_inv[GROUPS];
    __shared__ float s_gam[CCH], s_bet[CCH];

    const int tid  = threadIdx.x;
    const int lane = tid & 31;
    const int warp = tid >> 5;
    const int g = lane >> 2, t = lane & 3;
    const int wm0 = (warp >> 2) * 64;
    const int wn0 = (warp & 3) * 32;

    if (MODE == 0) {
        if (tid < GROUPS) {
            s_mu[tid]  = g_gnmu[z * GROUPS + tid];
            s_inv[tid] = g_gninv[z * GROUPS + tid];
        }
        for (int i = tid; i < CCH; i += 256) {
            s_gam[i] = gamma[i];
            s_bet[i] = beta[i];
        }
        __syncthreads();
    }

    float cfr[4][4][4];
    #pragma unroll
    for (int i = 0; i < 4; i++)
        #pragma unroll
        for (int j = 0; j < 4; j++)
            #pragma unroll
            for (int q = 0; q < 4; q++) cfr[i][j][q] = 0.f;

    const int amr = tid >> 1;
    const int akw = (tid & 1) * 8;
    const int bkp = tid >> 5;
    const int bln = tid & 31;

    for (int kt = 0; kt < K; kt += BK) {
        {   // stage A: W[m][k] -> As[m][k/2]
            const float* ap = Wg + (size_t)(m0 + amr) * lda + kt + akw * 2;
            uint32_t buf[8];
            #pragma unroll
            for (int it = 0; it < 4; it++) {
                float4 v = *(const float4*)(ap + it * 4);
                buf[it * 2 + 0] = pack_bf2(v.x, v.y);
                buf[it * 2 + 1] = pack_bf2(v.z, v.w);
            }
            uint32_t* dst = As + amr * SW + akw;
            *(uint4*)(dst)     = *(uint4*)(buf);
            *(uint4*)(dst + 4) = *(uint4*)(buf + 4);
        }
        {   // stage B: X[k][n] -> Bs[n][k/2]  (+ GN for MODE 0)
            #pragma unroll
            for (int half = 0; half < 2; half++) {
                int kp = bkp + half * 8;
                int ch = kt + 2 * kp;
                const float* r0 = Xg + Boff + (size_t)ch * ldb + n0;
                const float* r1 = r0 + ldb;
                float a0 = 1.f, c0 = 0.f, a1 = 1.f, c1 = 0.f;
                if (MODE == 0) {
                    float i0 = s_inv[ch >> 4],       m0v = s_mu[ch >> 4];
                    float i1 = s_inv[(ch + 1) >> 4], m1v = s_mu[(ch + 1) >> 4];
                    a0 = i0 * s_gam[ch];     c0 = s_bet[ch]     - m0v * a0;
                    a1 = i1 * s_gam[ch + 1]; c1 = s_bet[ch + 1] - m1v * a1;
                }
                #pragma unroll
                for (int c = 0; c < 4; c++) {
                    int n = bln + 32 * c;
                    float v0 = r0[n], v1 = r1[n];
                    if (MODE == 0) { v0 = v0 * a0 + c0; v1 = v1 * a1 + c1; }
                    Bs[n * SW + kp] = pack_bf2(v0, v1);
                }
            }
        }
        __syncthreads();

        #pragma unroll
        for (int kk = 0; kk < 2; kk++) {
            const int wb = kk * 8;
            uint32_t af[4][4], bf[4][2];
            #pragma unroll
            for (int mi = 0; mi < 4; mi++) {
                const uint32_t* p = As + (wm0 + mi * 16 + g) * SW + wb + t;
                af[mi][0] = p[0];
                af[mi][1] = p[8 * SW];
                af[mi][2] = p[4];
                af[mi][3] = p[8 * SW + 4];
            }
            #pragma unroll
            for (int ni = 0; ni < 4; ni++) {
                const uint32_t* p = Bs + (wn0 + ni * 8 + g) * SW + wb + t;
                bf[ni][0] = p[0];
                bf[ni][1] = p[4];
            }
            #pragma unroll
            for (int mi = 0; mi < 4; mi++)
                #pragma unroll
                for (int ni = 0; ni < 4; ni++)
                    MMA_BF16(cfr[mi][ni], af[mi], bf[ni]);
        }
        __syncthreads();
    }

    #pragma unroll
    for (int mi = 0; mi < 4; mi++) {
        #pragma unroll
        for (int rr = 0; rr < 2; rr++) {
            int grow = m0 + wm0 + mi * 16 + g + rr * 8;
            float bv = bias[grow];
            if (MODE == 0) {
                int sect = grow >> 9;                 // 0=Q 1=K 2=V
                int ch   = grow & 511;
                float sc = (sect == 0) ? ATT_SCALE : 1.f;
                __nv_bfloat16* dst = (sect == 0) ? g_qc
                                   : (sect == 1) ? g_kc : g_vb;
                size_t base = ((size_t)z * CCH + ch) * NPIX;
                #pragma unroll
                for (int ni = 0; ni < 4; ni++) {
                    int gcol = n0 + wn0 + ni * 8 + 2 * t;
                    float v0 = (cfr[mi][ni][rr * 2 + 0] + bv) * sc;
                    float v1 = (cfr[mi][ni][rr * 2 + 1] + bv) * sc;
                    *(uint32_t*)(dst + base + gcol) = pack_bf2(v0, v1);
                }
            } else {
                #pragma unroll
                for (int ni = 0; ni < 4; ni++) {
                    int gcol = n0 + wn0 + ni * 8 + 2 * t;
                    size_t idx = (size_t)z * CCH * NPIX + (size_t)grow * N + gcol;
                    Cg[idx]     = cfr[mi][ni][rr * 2 + 0] + bv + res[idx];
                    Cg[idx + 1] = cfr[mi][ni][rr * 2 + 1] + bv + res[idx + 1];
                }
            }
        }
    }
}

// ---------------- prep: bf16 transpose Q,K to [bh][qk][c] --------------------
__global__ void prep_qkT() {
    __shared__ __nv_bfloat16 ts[32][33];
    const int z = blockIdx.z;
    const int bh = z >> 1, which = z & 1;
    const int b = bh >> 2, h = bh & 3;
    const int c0 = blockIdx.x * 32, q0 = blockIdx.y * 32;
    const __nv_bfloat16* src = (which == 0 ? g_qc : g_kc)
        + ((size_t)b * CCH + h * HD) * NPIX;
    __nv_bfloat16* dst = (which == 0 ? g_qT : g_kT) + (size_t)bh * NPIX * HD;

    #pragma unroll
    for (int i = 0; i < 4; i++) {
        int c = c0 + threadIdx.y + i * 8;
        ts[threadIdx.y + i * 8][threadIdx.x] = src[(size_t)c * NPIX + q0 + threadIdx.x];
    }
    __syncthreads();
    #pragma unroll
    for (int i = 0; i < 4; i++) {
        int q = q0 + threadIdx.y + i * 8;
        dst[(size_t)q * HD + c0 + threadIdx.x] = ts[threadIdx.x][threadIdx.y + i * 8];
    }
}

// ---------------- flash attention: FA2 + cp.async double buffer --------------
#define LDW(p) (*(const uint32_t*)(p))
#define CPASY16(dst, src) \
    asm volatile("cp.async.cg.shared.global [%0], [%1], 16;" \
        :: "r"(dst), "l"(src))
#define CPCOMMIT() asm volatile("cp.async.commit_group;" ::: "memory")
#define CPWAIT0()  asm volatile("cp.async.wait_group 0;" ::: "memory")

#define FSTR 136
#define TILE_B (128 * FSTR * 2)        // 34816 bytes
#define QS_OFF  0
#define K0_OFF  (TILE_B)
#define V0_OFF  (2 * TILE_B)
#define K1_OFF  (3 * TILE_B)
#define V1_OFF  (4 * TILE_B)
#define FLASH_SMEM (5 * TILE_B + 128)

__global__ void __launch_bounds__(256, 1) flash_kernel() {
    extern __shared__ char smbuf[];
    __nv_bfloat16* Qs = (__nv_bfloat16*)(smbuf + QS_OFF);
    __nv_bfloat16* Kbuf[2] = { (__nv_bfloat16*)(smbuf + K0_OFF),
                               (__nv_bfloat16*)(smbuf + K1_OFF) };
    __nv_bfloat16* Vbuf[2] = { (__nv_bfloat16*)(smbuf + V0_OFF),
                               (__nv_bfloat16*)(smbuf + V1_OFF) };
    float* Ot = (float*)(smbuf + K0_OFF);   // reused after mainloop

    const int tid = threadIdx.x, lane = tid & 31, warp = tid >> 5;
    const int g = lane >> 2, t = lane & 3;
    const int wm = warp * 16;               // 16 query rows per warp
    const int bh = blockIdx.y, b = bh >> 2, h = bh & 3;
    const int q0 = blockIdx.x * 128;

    const __nv_bfloat16* qsrc = g_qT + (size_t)bh * NPIX * HD + (size_t)q0 * HD;
    const __nv_bfloat16* ksrc = g_kT + (size_t)bh * NPIX * HD;
    const __nv_bfloat16* vsrc = g_vb + ((size_t)b * CCH + h * HD) * NPIX;

    // async-stage K/V chunk 0 (R13-proven geometry: row=idx>>4, col8=(idx&15)*8;
    // 16B transfer == 8 bf16 == col8 stride -> full coverage)
    #pragma unroll
    for (int it = 0; it < 8; it++) {
        int idx = tid + it * 256;
        int row = idx >> 4, col8 = (idx & 15) * 8;
        CPASY16(smaddr(Kbuf[0] + row * FSTR + col8),
                ksrc + (size_t)row * HD + col8);
        CPASY16(smaddr(Vbuf[0] + row * FSTR + col8),
                vsrc + (size_t)row * NPIX + col8);
    }
    CPCOMMIT();

    // stage Q (plain loads): Qs[q][c]
    #pragma unroll
    for (int it = 0; it < 8; it++) {
        int idx = tid + it * 256;
        int row = idx >> 4, col8 = (idx & 15) * 8;
        *(uint4*)(Qs + row * FSTR + col8) = *(const uint4*)(qsrc + row * HD + col8);
    }

    float oacc[16][4];
    #pragma unroll
    for (int nj = 0; nj < 16; nj++)
        #pragma unroll
        for (int q = 0; q < 4; q++) oacc[nj][q] = 0.f;
    float m_run[2] = { -1e30f, -1e30f }, l_run[2] = { 0.f, 0.f };

    int cur = 0;
    for (int kc = 0; kc < 8; kc++) {
        CPWAIT0();
        __syncthreads();                   // all threads' chunk-kc data landed

        if (kc + 1 < 8) {                  // prefetch next chunk into other buf
            const __nv_bfloat16* kn = ksrc + (size_t)(kc + 1) * 128 * HD;
            const __nv_bfloat16* vn = vsrc + (kc + 1) * 128;
            #pragma unroll
            for (int it = 0; it < 8; it++) {
                int idx = tid + it * 256;
                int row = idx >> 4, col8 = (idx & 15) * 8;
                CPASY16(smaddr(Kbuf[cur ^ 1] + row * FSTR + col8),
                        kn + (size_t)row * HD + col8);
                CPASY16(smaddr(Vbuf[cur ^ 1] + row * FSTR + col8),
                        vn + (size_t)row * NPIX + col8);
            }
            CPCOMMIT();
        }

        const __nv_bfloat16* Ks = Kbuf[cur];
        const __nv_bfloat16* Vs = Vbuf[cur];

        // ---- S = Q K^T : warp rows wm..wm+15, all 128 keys ----
        float sacc[16][4];
        #pragma unroll
        for (int ni = 0; ni < 16; ni++)
            #pragma unroll
            for (int q = 0; q < 4; q++) sacc[ni][q] = 0.f;
        #pragma unroll
        for (int ks = 0; ks < 8; ks++) {
            const int kb = ks * 16;
            uint32_t af[4];
            const __nv_bfloat16* pq = Qs + (wm + g) * FSTR + kb + 2 * t;
            af[0] = LDW(pq);
            af[1] = LDW(pq + 8 * FSTR);
            af[2] = LDW(pq + 8);
            af[3] = LDW(pq + 8 * FSTR + 8);
            #pragma unroll
            for (int ni = 0; ni < 16; ni++) {
                uint32_t bf[2];
                const __nv_bfloat16* pk = Ks + (ni * 8 + g) * FSTR + kb + 2 * t;
                bf[0] = LDW(pk);
                bf[1] = LDW(pk + 8);
                MMA_BF16(sacc[ni], af, bf);
            }
        }

        // ---- online softmax: warp-local (shfl over t lanes only) ----
        float mnew[2], al[2];
        #pragma unroll
        for (int rr = 0; rr < 2; rr++) {
            float mx = -1e30f;
            #pragma unroll
            for (int ni = 0; ni < 16; ni++)
                mx = fmaxf(mx, fmaxf(sacc[ni][2 * rr], sacc[ni][2 * rr + 1]));
            mx = fmaxf(mx, __shfl_xor_sync(0xffffffffu, mx, 1));
            mx = fmaxf(mx, __shfl_xor_sync(0xffffffffu, mx, 2));
            float mn = fmaxf(m_run[rr], mx);
            al[rr] = __expf(m_run[rr] - mn);
            mnew[rr] = mn;
        }
        uint32_t pp[16][2];
        float lloc[2] = { 0.f, 0.f };
        #pragma unroll
        for (int ni = 0; ni < 16; ni++) {
            float p0 = __expf(sacc[ni][0] - mnew[0]);
            float p1 = __expf(sacc[ni][1] - mnew[0]);
            float p2 = __expf(sacc[ni][2] - mnew[1]);
            float p3 = __expf(sacc[ni][3] - mnew[1]);
            lloc[0] += p0 + p1;
            lloc[1] += p2 + p3;
            pp[ni][0] = pack_bf2(p0, p1);
            pp[ni][1] = pack_bf2(p2, p3);
        }
        #pragma unroll
        for (int rr = 0; rr < 2; rr++) {
            float s = lloc[rr];
            s += __shfl_xor_sync(0xffffffffu, s, 1);
            s += __shfl_xor_sync(0xffffffffu, s, 2);
            l_run[rr] = l_run[rr] * al[rr] + s;
            m_run[rr] = mnew[rr];
        }
        #pragma unroll
        for (int nj = 0; nj < 16; nj++) {
            oacc[nj][0] *= al[0]; oacc[nj][1] *= al[0];
            oacc[nj][2] *= al[1]; oacc[nj][3] *= al[1];
        }

        // ---- O += P V^T : P in registers (A-frag = pp), B from Vs ----
        #pragma unroll
        for (int ks = 0; ks < 8; ks++) {
            uint32_t af[4] = { pp[2 * ks][0], pp[2 * ks][1],
                               pp[2 * ks + 1][0], pp[2 * ks + 1][1] };
            const int kb = ks * 16;
            #pragma unroll
            for (int nj = 0; nj < 16; nj++) {
                uint32_t bf[2];
                const __nv_bfloat16* pv = Vs + (nj * 8 + g) * FSTR + kb + 2 * t;
                bf[0] = LDW(pv);
                bf[1] = LDW(pv + 8);
                MMA_BF16(oacc[nj], af, bf);
            }
        }
        cur ^= 1;
    }

    // ---- epilogue: smem transpose -> coalesced [c][q] store ----
    __syncthreads();                       // before reusing K/V smem as Ot
    float inv0 = 1.f / l_run[0], inv1 = 1.f / l_run[1];
    #pragma unroll
    for (int nj = 0; nj < 16; nj++)
        #pragma unroll
        for (int q = 0; q < 4; q++) {
            int col = nj * 8 + 2 * t + (q & 1);              // c
            int row = wm + g + 8 * (q >> 1);                 // q
            Ot[col * 132 + row] = oacc[nj][q] * ((q >> 1) ? inv1 : inv0);
        }
    __syncthreads();
    float* og = g_att + ((size_t)b * CCH + h * HD) * NPIX + q0;
    #pragma unroll
    for (int it = 0; it < 16; it++) {
        int idx = tid + it * 256;
        int c = idx >> 5, q4 = (idx & 31) << 2;
        *(float4*)(og + (size_t)c * NPIX + q4) = *(const float4*)(Ot + c * 132 + q4);
    }
}

// ---------------- launch -----------------------------------------------------
extern "C" void kernel_launch(void* const* d_in, const int* in_sizes, int n_in,
                              void* d_out, int out_size) {
    const float* x      = (const float*)d_in[0];
    const float* gamma  = (const float*)d_in[1];
    const float* beta   = (const float*)d_in[2];
    const float* w_qkv  = (const float*)d_in[3];
    const float* b_qkv  = (const float*)d_in[4];
    const float* w_proj = (const float*)d_in[5];
    const float* b_proj = (const float*)d_in[6];
    float* out = (float*)d_out;

    float* att;
    cudaGetSymbolAddress((void**)&att, g_att);

    cudaFuncSetAttribute(flash_kernel,
        cudaFuncAttributeMaxDynamicSharedMemorySize, FLASH_SMEM);

    // 1) GroupNorm statistics
    gn_stats<<<BATCH * GROUPS, 256>>>(x);

    // 2) QKV projection (bf16, GN fused in, bf16 Q/K/V out)
    bf16_gemm<0><<<dim3(NPIX / BN, 3 * CCH / BM, BATCH), 256>>>(
        w_qkv, x, nullptr, b_qkv, nullptr, gamma, beta,
        3 * CCH, NPIX, CCH, CCH, NPIX);

    // 3) prep: Q/K bf16 transpose to [bh][q/key][c]
    prep_qkT<<<dim3(HD / 32, NPIX / 32, NBH * 2), dim3(32, 8)>>>();

    // 4) fused flash attention (bf16, FA2 layout, cp.async double buffer)
    flash_kernel<<<dim3(NPIX / 128, NBH), 256, FLASH_SMEM>>>();

    // 5) proj + bias + residual (bf16)
    bf16_gemm<3><<<dim3(NPIX / BN, CCH / BM, BATCH), 256>>>(
        w_proj, att, out, b_proj, x, nullptr, nullptr,
        CCH, NPIX, CCH, CCH, NPIX);
}

// round 15
// speedup vs baseline: 1.0588x; 1.0588x over previous
#include <cuda_runtime.h>
#include <cuda_bf16.h>
#include <cstdint>

#define BATCH   16
#define CCH     512
#define NPIX    1024          // 32*32
#define HEADS   4
#define HD      128           // CCH / HEADS
#define GROUPS  32
#define CPG     (CCH / GROUPS)   // 16
#define GEPS    1e-5f
#define ATT_SCALE 0.088388347648318447f   // 128^-0.5
#define NBH     (BATCH * HEADS)           // 64

// ---------------- scratch (device globals; no allocations allowed) ----------
__device__ float g_att[BATCH * CCH * NPIX];                 // 33.5 MB fp32
__device__ float g_gnmu [BATCH * GROUPS];
__device__ float g_gninv[BATCH * GROUPS];
__device__ __nv_bfloat16 g_qc[(size_t)BATCH * CCH * NPIX];  // [b][c][q], scaled
__device__ __nv_bfloat16 g_kc[(size_t)BATCH * CCH * NPIX];  // [b][c][q]
__device__ __nv_bfloat16 g_vb[(size_t)BATCH * CCH * NPIX];  // [b][c][key]
__device__ __nv_bfloat16 g_qT[(size_t)NBH * NPIX * HD];     // [bh][q][c]
__device__ __nv_bfloat16 g_kT[(size_t)NBH * NPIX * HD];     // [bh][key][c]

__device__ __forceinline__ uint32_t pack_bf2(float a, float b) {
    __nv_bfloat162 h = __floats2bfloat162_rn(a, b);
    return *(uint32_t*)&h;
}

// ---------------- GroupNorm stats only ---------------------------------------
__global__ void gn_stats(const float* __restrict__ x) {
    const int bg = blockIdx.x;
    const int b  = bg / GROUPS;
    const int g  = bg % GROUPS;
    const int M  = CPG * NPIX;                  // 16384
    const float* xp = x + ((size_t)b * CCH + (size_t)g * CPG) * NPIX;

    float s = 0.f, ss = 0.f;
    for (int i = threadIdx.x; i < M; i += blockDim.x) {
        float v = xp[i];
        s += v; ss += v * v;
    }
    __shared__ float red[64];
    #pragma unroll
    for (int o = 16; o; o >>= 1) {
        s  += __shfl_xor_sync(0xffffffffu, s,  o);
        ss += __shfl_xor_sync(0xffffffffu, ss, o);
    }
    const int warp = threadIdx.x >> 5, lane = threadIdx.x & 31;
    if (lane == 0) { red[warp] = s; red[warp + 32] = ss; }
    __syncthreads();
    if (threadIdx.x == 0) {
        float s2 = 0.f, ss2 = 0.f;
        #pragma unroll
        for (int i = 0; i < 8; i++) { s2 += red[i]; ss2 += red[i + 32]; }
        float mu  = s2 / (float)M;
        float var = ss2 / (float)M - mu * mu;
        g_gnmu[bg]  = mu;
        g_gninv[bg] = rsqrtf(var + GEPS);
    }
}

// ---------------- bf16 MMA GEMM with gmem->reg prefetch ----------------------
#define BM 128
#define BN 128
#define BK 32
#define SW 20

#define MMA_BF16(c, a, b) \
    asm volatile("mma.sync.aligned.m16n8k16.row.col.f32.bf16.bf16.f32 " \
        "{%0,%1,%2,%3},{%4,%5,%6,%7},{%8,%9},{%0,%1,%2,%3};" \
        : "+f"((c)[0]), "+f"((c)[1]), "+f"((c)[2]), "+f"((c)[3]) \
        : "r"((a)[0]), "r"((a)[1]), "r"((a)[2]), "r"((a)[3]), \
          "r"((b)[0]), "r"((b)[1]))

template<int MODE>
__global__ void __launch_bounds__(256, 2)
bf16_gemm(const float* __restrict__ Wg, const float* __restrict__ Xg,
          float* __restrict__ Cg,
          const float* __restrict__ bias, const float* __restrict__ res,
          const float* __restrict__ gamma, const float* __restrict__ beta,
          int M, int N, int K, int lda, int ldb) {
    const int z  = blockIdx.z;
    const int m0 = blockIdx.y * BM;
    const int n0 = blockIdx.x * BN;
    const size_t Boff = (size_t)z * CCH * NPIX;

    __shared__ uint32_t As[BM * SW];
    __shared__ uint32_t Bs[BN * SW];
    __shared__ float s_mu[GROUPS], s_inv[GROUPS];
    __shared__ float s_gam[CCH], s_bet[CCH];

    const int tid  = threadIdx.x;
    const int lane = tid & 31;
    const int warp = tid >> 5;
    const int g = lane >> 2, t = lane & 3;
    const int wm0 = (warp >> 2) * 64;
    const int wn0 = (warp & 3) * 32;

    if (MODE == 0) {
        if (tid < GROUPS) {
            s_mu[tid]  = g_gnmu[z * GROUPS + tid];
            s_inv[tid] = g_gninv[z * GROUPS + tid];
        }
        for (int i = tid; i < CCH; i += 256) {
            s_gam[i] = gamma[i];
            s_bet[i] = beta[i];
        }
        __syncthreads();
    }

    float cfr[4][4][4];
    #pragma unroll
    for (int i = 0; i < 4; i++)
        #pragma unroll
        for (int j = 0; j < 4; j++)
            #pragma unroll
            for (int q = 0; q < 4; q++) cfr[i][j][q] = 0.f;

    const int amr = tid >> 1;              // A staging row
    const int akw = (tid & 1) * 8;         // A word offset
    const int bkp = tid >> 5;              // B k-pair base
    const int bln = tid & 31;              // B lane n

    // ---- prefetch registers ----
    float4 ar[2];
    float  br[2][2][4];                    // [half][row01][c]

    // preload tile kt=0
    {
        const float* ap = Wg + (size_t)(m0 + amr) * lda + akw * 2;
        ar[0] = *(const float4*)(ap);
        ar[1] = *(const float4*)(ap + 4);
        #pragma unroll
        for (int half = 0; half < 2; half++) {
            int kp = bkp + half * 8;
            const float* r0 = Xg + Boff + (size_t)(2 * kp) * ldb + n0;
            const float* r1 = r0 + ldb;
            #pragma unroll
            for (int c = 0; c < 4; c++) {
                int n = bln + 32 * c;
                br[half][0][c] = r0[n];
                br[half][1][c] = r1[n];
            }
        }
    }

    for (int kt = 0; kt < K; kt += BK) {
        __syncthreads();                   // previous MMA done; smem writable
        {   // store A regs -> smem (convert at store)
            uint32_t buf[8];
            buf[0] = pack_bf2(ar[0].x, ar[0].y);
            buf[1] = pack_bf2(ar[0].z, ar[0].w);
            buf[2] = pack_bf2(ar[1].x, ar[1].y);
            buf[3] = pack_bf2(ar[1].z, ar[1].w);
            // second float4 pair loaded as ar[0..1] covers 8 floats = words 0..3;
            // we need 8 words: reload pattern below keeps original coverage
            uint32_t* dst = As + amr * SW + akw;
            *(uint4*)(dst) = *(uint4*)(buf);
        }
        {   // A covers 16 floats per thread originally: handle second half
            // (akw*2+8 .. akw*2+15) stored as words akw+4..akw+7
        }
        {   // store B regs -> smem with GN applied for THIS tile's channels
            #pragma unroll
            for (int half = 0; half < 2; half++) {
                int kp = bkp + half * 8;
                int ch = kt + 2 * kp;
                float a0 = 1.f, c0 = 0.f, a1 = 1.f, c1 = 0.f;
                if (MODE == 0) {
                    float i0 = s_inv[ch >> 4],       m0v = s_mu[ch >> 4];
                    float i1 = s_inv[(ch + 1) >> 4], m1v = s_mu[(ch + 1) >> 4];
                    a0 = i0 * s_gam[ch];     c0 = s_bet[ch]     - m0v * a0;
                    a1 = i1 * s_gam[ch + 1]; c1 = s_bet[ch + 1] - m1v * a1;
                }
                #pragma unroll
                for (int c = 0; c < 4; c++) {
                    int n = bln + 32 * c;
                    float v0 = br[half][0][c], v1 = br[half][1][c];
                    if (MODE == 0) { v0 = v0 * a0 + c0; v1 = v1 * a1 + c1; }
                    Bs[n * SW + kp] = pack_bf2(v0, v1);
                }
            }
        }
        __syncthreads();                   // staged tile visible

        // prefetch next tile's gmem data into regs (overlaps MMA below)
        if (kt + BK < K) {
            const float* ap = Wg + (size_t)(m0 + amr) * lda + (kt + BK) + akw * 2;
            ar[0] = *(const float4*)(ap);
            ar[1] = *(const float4*)(ap + 4);
            #pragma unroll
            for (int half = 0; half < 2; half++) {
                int kp = bkp + half * 8;
                const float* r0 = Xg + Boff + (size_t)(kt + BK + 2 * kp) * ldb + n0;
                const float* r1 = r0 + ldb;
                #pragma unroll
                for (int c = 0; c < 4; c++) {
                    int n = bln + 32 * c;
                    br[half][0][c] = r0[n];
                    br[half][1][c] = r1[n];
                }
            }
        }

        #pragma unroll
        for (int kk = 0; kk < 2; kk++) {
            const int wb = kk * 8;
            uint32_t af[4][4], bf[4][2];
            #pragma unroll
            for (int mi = 0; mi < 4; mi++) {
                const uint32_t* p = As + (wm0 + mi * 16 + g) * SW + wb + t;
                af[mi][0] = p[0];
                af[mi][1] = p[8 * SW];
                af[mi][2] = p[4];
                af[mi][3] = p[8 * SW + 4];
            }
            #pragma unroll
            for (int ni = 0; ni < 4; ni++) {
                const uint32_t* p = Bs + (wn0 + ni * 8 + g) * SW + wb + t;
                bf[ni][0] = p[0];
                bf[ni][1] = p[4];
            }
            #pragma unroll
            for (int mi = 0; mi < 4; mi++)
                #pragma unroll
                for (int ni = 0; ni < 4; ni++)
                    MMA_BF16(cfr[mi][ni], af[mi], bf[ni]);
        }
    }

    #pragma unroll
    for (int mi = 0; mi < 4; mi++) {
        #pragma unroll
        for (int rr = 0; rr < 2; rr++) {
            int grow = m0 + wm0 + mi * 16 + g + rr * 8;
            float bv = bias[grow];
            if (MODE == 0) {
                int sect = grow >> 9;                 // 0=Q 1=K 2=V
                int ch   = grow & 511;
                float sc = (sect == 0) ? ATT_SCALE : 1.f;
                __nv_bfloat16* dst = (sect == 0) ? g_qc
                                   : (sect == 1) ? g_kc : g_vb;
                size_t base = ((size_t)z * CCH + ch) * NPIX;
                #pragma unroll
                for (int ni = 0; ni < 4; ni++) {
                    int gcol = n0 + wn0 + ni * 8 + 2 * t;
                    float v0 = (cfr[mi][ni][rr * 2 + 0] + bv) * sc;
                    float v1 = (cfr[mi][ni][rr * 2 + 1] + bv) * sc;
                    *(uint32_t*)(dst + base + gcol) = pack_bf2(v0, v1);
                }
            } else {
                #pragma unroll
                for (int ni = 0; ni < 4; ni++) {
                    int gcol = n0 + wn0 + ni * 8 + 2 * t;
                    size_t idx = (size_t)z * CCH * NPIX + (size_t)grow * N + gcol;
                    Cg[idx]     = cfr[mi][ni][rr * 2 + 0] + bv + res[idx];
                    Cg[idx + 1] = cfr[mi][ni][rr * 2 + 1] + bv + res[idx + 1];
                }
            }
        }
    }
}

// Fixed A coverage: each thread covers 16 floats of W (akw*2 .. akw*2+15).
// The prefetch version above loads ar[0..1] = 8 floats only; to keep coverage
// identical to the proven R13 staging we widen to 4 float4 registers.
// (Handled by template re-specialization below — see bf16_gemm_full.)
// NOTE: the kernel above is NOT launched; bf16_gemm_full is the real one.

template<int MODE>
__global__ void __launch_bounds__(256, 2)
bf16_gemm_full(const float* __restrict__ Wg, const float* __restrict__ Xg,
               float* __restrict__ Cg,
               const float* __restrict__ bias, const float* __restrict__ res,
               const float* __restrict__ gamma, const float* __restrict__ beta,
               int M, int N, int K, int lda, int ldb) {
    const int z  = blockIdx.z;
    const int m0 = blockIdx.y * BM;
    const int n0 = blockIdx.x * BN;
    const size_t Boff = (size_t)z * CCH * NPIX;

    __shared__ uint32_t As[BM * SW];
    __shared__ uint32_t Bs[BN * SW];
    __shared__ float s_mu[GROUPS], s_inv[GROUPS];
    __shared__ float s_gam[CCH], s_bet[CCH];

    const int tid  = threadIdx.x;
    const int lane = tid & 31;
    const int warp = tid >> 5;
    const int g = lane >> 2, t = lane & 3;
    const int wm0 = (warp >> 2) * 64;
    const int wn0 = (warp & 3) * 32;

    if (MODE == 0) {
        if (tid < GROUPS) {
            s_mu[tid]  = g_gnmu[z * GROUPS + tid];
            s_inv[tid] = g_gninv[z * GROUPS + tid];
        }
        for (int i = tid; i < CCH; i += 256) {
            s_gam[i] = gamma[i];
            s_bet[i] = beta[i];
        }
        __syncthreads();
    }

    float cfr[4][4][4];
    #pragma unroll
    for (int i = 0; i < 4; i++)
        #pragma unroll
        for (int j = 0; j < 4; j++)
            #pragma unroll
            for (int q = 0; q < 4; q++) cfr[i][j][q] = 0.f;

    const int amr = tid >> 1;
    const int akw = (tid & 1) * 8;         // word offset; covers floats akw*2..akw*2+15
    const int bkp = tid >> 5;
    const int bln = tid & 31;

    float4 ar[4];                          // 16 floats of A
    float  br[2][2][4];                    // 16 floats of B

    {   // preload kt = 0
        const float* ap = Wg + (size_t)(m0 + amr) * lda + akw * 2;
        #pragma unroll
        for (int i = 0; i < 4; i++) ar[i] = *(const float4*)(ap + i * 4);
        #pragma unroll
        for (int half = 0; half < 2; half++) {
            int kp = bkp + half * 8;
            const float* r0 = Xg + Boff + (size_t)(2 * kp) * ldb + n0;
            const float* r1 = r0 + ldb;
            #pragma unroll
            for (int c = 0; c < 4; c++) {
                int n = bln + 32 * c;
                br[half][0][c] = r0[n];
                br[half][1][c] = r1[n];
            }
        }
    }

    for (int kt = 0; kt < K; kt += BK) {
        __syncthreads();
        {   // store A: regs -> smem words akw..akw+7
            uint32_t buf[8];
            #pragma unroll
            for (int i = 0; i < 4; i++) {
                buf[i * 2 + 0] = pack_bf2(ar[i].x, ar[i].y);
                buf[i * 2 + 1] = pack_bf2(ar[i].z, ar[i].w);
            }
            uint32_t* dst = As + amr * SW + akw;
            *(uint4*)(dst)     = *(uint4*)(buf);
            *(uint4*)(dst + 4) = *(uint4*)(buf + 4);
        }
        {   // store B with GN for THIS tile's channels
            #pragma unroll
            for (int half = 0; half < 2; half++) {
                int kp = bkp + half * 8;
                int ch = kt + 2 * kp;
                float a0 = 1.f, c0 = 0.f, a1 = 1.f, c1 = 0.f;
                if (MODE == 0) {
                    float i0 = s_inv[ch >> 4],       m0v = s_mu[ch >> 4];
                    float i1 = s_inv[(ch + 1) >> 4], m1v = s_mu[(ch + 1) >> 4];
                    a0 = i0 * s_gam[ch];     c0 = s_bet[ch]     - m0v * a0;
                    a1 = i1 * s_gam[ch + 1]; c1 = s_bet[ch + 1] - m1v * a1;
                }
                #pragma unroll
                for (int c = 0; c < 4; c++) {
                    int n = bln + 32 * c;
                    float v0 = br[half][0][c], v1 = br[half][1][c];
                    if (MODE == 0) { v0 = v0 * a0 + c0; v1 = v1 * a1 + c1; }
                    Bs[n * SW + kp] = pack_bf2(v0, v1);
                }
            }
        }
        __syncthreads();

        if (kt + BK < K) {                 // prefetch next tile (overlaps MMA)
            const float* ap = Wg + (size_t)(m0 + amr) * lda + (kt + BK) + akw * 2;
            #pragma unroll
            for (int i = 0; i < 4; i++) ar[i] = *(const float4*)(ap + i * 4);
            #pragma unroll
            for (int half = 0; half < 2; half++) {
                int kp = bkp + half * 8;
                const float* r0 = Xg + Boff + (size_t)(kt + BK + 2 * kp) * ldb + n0;
                const float* r1 = r0 + ldb;
                #pragma unroll
                for (int c = 0; c < 4; c++) {
                    int n = bln + 32 * c;
                    br[half][0][c] = r0[n];
                    br[half][1][c] = r1[n];
                }
            }
        }

        #pragma unroll
        for (int kk = 0; kk < 2; kk++) {
            const int wb = kk * 8;
            uint32_t af[4][4], bf[4][2];
            #pragma unroll
            for (int mi = 0; mi < 4; mi++) {
                const uint32_t* p = As + (wm0 + mi * 16 + g) * SW + wb + t;
                af[mi][0] = p[0];
                af[mi][1] = p[8 * SW];
                af[mi][2] = p[4];
                af[mi][3] = p[8 * SW + 4];
            }
            #pragma unroll
            for (int ni = 0; ni < 4; ni++) {
                const uint32_t* p = Bs + (wn0 + ni * 8 + g) * SW + wb + t;
                bf[ni][0] = p[0];
                bf[ni][1] = p[4];
            }
            #pragma unroll
            for (int mi = 0; mi < 4; mi++)
                #pragma unroll
                for (int ni = 0; ni < 4; ni++)
                    MMA_BF16(cfr[mi][ni], af[mi], bf[ni]);
        }
    }

    #pragma unroll
    for (int mi = 0; mi < 4; mi++) {
        #pragma unroll
        for (int rr = 0; rr < 2; rr++) {
            int grow = m0 + wm0 + mi * 16 + g + rr * 8;
            float bv = bias[grow];
            if (MODE == 0) {
                int sect = grow >> 9;
                int ch   = grow & 511;
                float sc = (sect == 0) ? ATT_SCALE : 1.f;
                __nv_bfloat16* dst = (sect == 0) ? g_qc
                                   : (sect == 1) ? g_kc : g_vb;
                size_t base = ((size_t)z * CCH + ch) * NPIX;
                #pragma unroll
                for (int ni = 0; ni < 4; ni++) {
                    int gcol = n0 + wn0 + ni * 8 + 2 * t;
                    float v0 = (cfr[mi][ni][rr * 2 + 0] + bv) * sc;
                    float v1 = (cfr[mi][ni][rr * 2 + 1] + bv) * sc;
                    *(uint32_t*)(dst + base + gcol) = pack_bf2(v0, v1);
                }
            } else {
                #pragma unroll
                for (int ni = 0; ni < 4; ni++) {
                    int gcol = n0 + wn0 + ni * 8 + 2 * t;
                    size_t idx = (size_t)z * CCH * NPIX + (size_t)grow * N + gcol;
                    Cg[idx]     = cfr[mi][ni][rr * 2 + 0] + bv + res[idx];
                    Cg[idx + 1] = cfr[mi][ni][rr * 2 + 1] + bv + res[idx + 1];
                }
            }
        }
    }
}

// ---------------- prep: bf16 transpose Q,K to [bh][qk][c] --------------------
__global__ void prep_qkT() {
    __shared__ __nv_bfloat16 ts[32][33];
    const int z = blockIdx.z;
    const int bh = z >> 1, which = z & 1;
    const int b = bh >> 2, h = bh & 3;
    const int c0 = blockIdx.x * 32, q0 = blockIdx.y * 32;
    const __nv_bfloat16* src = (which == 0 ? g_qc : g_kc)
        + ((size_t)b * CCH + h * HD) * NPIX;
    __nv_bfloat16* dst = (which == 0 ? g_qT : g_kT) + (size_t)bh * NPIX * HD;

    #pragma unroll
    for (int i = 0; i < 4; i++) {
        int c = c0 + threadIdx.y + i * 8;
        ts[threadIdx.y + i * 8][threadIdx.x] = src[(size_t)c * NPIX + q0 + threadIdx.x];
    }
    __syncthreads();
    #pragma unroll
    for (int i = 0; i < 4; i++) {
        int q = q0 + threadIdx.y + i * 8;
        dst[(size_t)q * HD + c0 + threadIdx.x] = ts[threadIdx.x][threadIdx.y + i * 8];
    }
}

// ---------------- flash attention: R13-proven (reverted from cp.async) -------
#define LDW(p) (*(const uint32_t*)(p))
#define FSTR 136
#define TILE_B (128 * FSTR * 2)        // 34816 bytes
#define QS_OFF  0
#define K_OFF   (TILE_B)
#define V_OFF   (2 * TILE_B)
#define FLASH_SMEM (3 * TILE_B + 128)

__global__ void __launch_bounds__(256, 1) flash_kernel() {
    extern __shared__ char smbuf[];
    __nv_bfloat16* Qs = (__nv_bfloat16*)(smbuf + QS_OFF);
    __nv_bfloat16* Ks = (__nv_bfloat16*)(smbuf + K_OFF);
    __nv_bfloat16* Vs = (__nv_bfloat16*)(smbuf + V_OFF);
    float* Ot = (float*)(smbuf + K_OFF);   // reused after mainloop

    const int tid = threadIdx.x, lane = tid & 31, warp = tid >> 5;
    const int g = lane >> 2, t = lane & 3;
    const int wm = warp * 16;               // 16 query rows per warp
    const int bh = blockIdx.y, b = bh >> 2, h = bh & 3;
    const int q0 = blockIdx.x * 128;

    const __nv_bfloat16* qsrc = g_qT + (size_t)bh * NPIX * HD + (size_t)q0 * HD;
    const __nv_bfloat16* ksrc = g_kT + (size_t)bh * NPIX * HD;
    const __nv_bfloat16* vsrc = g_vb + ((size_t)b * CCH + h * HD) * NPIX;

    #pragma unroll
    for (int it = 0; it < 8; it++) {
        int idx = tid + it * 256;
        int row = idx >> 4, col8 = (idx & 15) * 8;
        *(uint4*)(Qs + row * FSTR + col8) = *(const uint4*)(qsrc + row * HD + col8);
    }

    float oacc[16][4];
    #pragma unroll
    for (int nj = 0; nj < 16; nj++)
        #pragma unroll
        for (int q = 0; q < 4; q++) oacc[nj][q] = 0.f;
    float m_run[2] = { -1e30f, -1e30f }, l_run[2] = { 0.f, 0.f };

    for (int kc = 0; kc < 8; kc++) {
        __syncthreads();
        #pragma unroll
        for (int it = 0; it < 8; it++) {
            int idx = tid + it * 256;
            int row = idx >> 4, col8 = (idx & 15) * 8;
            *(uint4*)(Ks + row * FSTR + col8) =
                *(const uint4*)(ksrc + (size_t)(kc * 128 + row) * HD + col8);
            *(uint4*)(Vs + row * FSTR + col8) =
                *(const uint4*)(vsrc + (size_t)row * NPIX + kc * 128 + col8);
        }
        __syncthreads();

        float sacc[16][4];
        #pragma unroll
        for (int ni = 0; ni < 16; ni++)
            #pragma unroll
            for (int q = 0; q < 4; q++) sacc[ni][q] = 0.f;
        #pragma unroll
        for (int ks = 0; ks < 8; ks++) {
            const int kb = ks * 16;
            uint32_t af[4];
            const __nv_bfloat16* pq = Qs + (wm + g) * FSTR + kb + 2 * t;
            af[0] = LDW(pq);
            af[1] = LDW(pq + 8 * FSTR);
            af[2] = LDW(pq + 8);
            af[3] = LDW(pq + 8 * FSTR + 8);
            #pragma unroll
            for (int ni = 0; ni < 16; ni++) {
                uint32_t bf[2];
                const __nv_bfloat16* pk = Ks + (ni * 8 + g) * FSTR + kb + 2 * t;
                bf[0] = LDW(pk);
                bf[1] = LDW(pk + 8);
                MMA_BF16(sacc[ni], af, bf);
            }
        }

        float mnew[2], al[2];
        #pragma unroll
        for (int rr = 0; rr < 2; rr++) {
            float mx = -1e30f;
            #pragma unroll
            for (int ni = 0; ni < 16; ni++)
                mx = fmaxf(mx, fmaxf(sacc[ni][2 * rr], sacc[ni][2 * rr + 1]));
            mx = fmaxf(mx, __shfl_xor_sync(0xffffffffu, mx, 1));
            mx = fmaxf(mx, __shfl_xor_sync(0xffffffffu, mx, 2));
            float mn = fmaxf(m_run[rr], mx);
            al[rr] = __expf(m_run[rr] - mn);
            mnew[rr] = mn;
        }
        uint32_t pp[16][2];
        float lloc[2] = { 0.f, 0.f };
        #pragma unroll
        for (int ni = 0; ni < 16; ni++) {
            float p0 = __expf(sacc[ni][0] - mnew[0]);
            float p1 = __expf(sacc[ni][1] - mnew[0]);
            float p2 = __expf(sacc[ni][2] - mnew[1]);
            float p3 = __expf(sacc[ni][3] - mnew[1]);
            lloc[0] += p0 + p1;
            lloc[1] += p2 + p3;
            pp[ni][0] = pack_bf2(p0, p1);
            pp[ni][1] = pack_bf2(p2, p3);
        }
        #pragma unroll
        for (int rr = 0; rr < 2; rr++) {
            float s = lloc[rr];
            s += __shfl_xor_sync(0xffffffffu, s, 1);
            s += __shfl_xor_sync(0xffffffffu, s, 2);
            l_run[rr] = l_run[rr] * al[rr] + s;
            m_run[rr] = mnew[rr];
        }
        #pragma unroll
        for (int nj = 0; nj < 16; nj++) {
            oacc[nj][0] *= al[0]; oacc[nj][1] *= al[0];
            oacc[nj][2] *= al[1]; oacc[nj][3] *= al[1];
        }

        #pragma unroll
        for (int ks = 0; ks < 8; ks++) {
            uint32_t af[4] = { pp[2 * ks][0], pp[2 * ks][1],
                               pp[2 * ks + 1][0], pp[2 * ks + 1][1] };
            const int kb = ks * 16;
            #pragma unroll
            for (int nj = 0; nj < 16; nj++) {
                uint32_t bf[2];
                const __nv_bfloat16* pv = Vs + (nj * 8 + g) * FSTR + kb + 2 * t;
                bf[0] = LDW(pv);
                bf[1] = LDW(pv + 8);
                MMA_BF16(oacc[nj], af, bf);
            }
        }
    }

    __syncthreads();
    float inv0 = 1.f / l_run[0], inv1 = 1.f / l_run[1];
    #pragma unroll
    for (int nj = 0; nj < 16; nj++)
        #pragma unroll
        for (int q = 0; q < 4; q++) {
            int col = nj * 8 + 2 * t + (q & 1);
            int row = wm + g + 8 * (q >> 1);
            Ot[col * 132 + row] = oacc[nj][q] * ((q >> 1) ? inv1 : inv0);
        }
    __syncthreads();
    float* og = g_att + ((size_t)b * CCH + h * HD) * NPIX + q0;
    #pragma unroll
    for (int it = 0; it < 16; it++) {
        int idx = tid + it * 256;
        int c = idx >> 5, q4 = (idx & 31) << 2;
        *(float4*)(og + (size_t)c * NPIX + q4) = *(const float4*)(Ot + c * 132 + q4);
    }
}

// ---------------- launch -----------------------------------------------------
extern "C" void kernel_launch(void* const* d_in, const int* in_sizes, int n_in,
                              void* d_out, int out_size) {
    const float* x      = (const float*)d_in[0];
    const float* gamma  = (const float*)d_in[1];
    const float* beta   = (const float*)d_in[2];
    const float* w_qkv  = (const float*)d_in[3];
    const float* b_qkv  = (const float*)d_in[4];
    const float* w_proj = (const float*)d_in[5];
    const float* b_proj = (const float*)d_in[6];
    float* out = (float*)d_out;

    float* att;
    cudaGetSymbolAddress((void**)&att, g_att);

    cudaFuncSetAttribute(flash_kernel,
        cudaFuncAttributeMaxDynamicSharedMemorySize, FLASH_SMEM);

    // 1) GroupNorm statistics
    gn_stats<<<BATCH * GROUPS, 256>>>(x);

    // 2) QKV projection (bf16, GN fused, prefetch pipelined)
    bf16_gemm_full<0><<<dim3(NPIX / BN, 3 * CCH / BM, BATCH), 256>>>(
        w_qkv, x, nullptr, b_qkv, nullptr, gamma, beta,
        3 * CCH, NPIX, CCH, CCH, NPIX);

    // 3) prep: Q/K bf16 transpose to [bh][q/key][c]
    prep_qkT<<<dim3(HD / 32, NPIX / 32, NBH * 2), dim3(32, 8)>>>();

    // 4) fused flash attention (R13-proven)
    flash_kernel<<<dim3(NPIX / 128, NBH), 256, FLASH_SMEM>>>();

    // 5) proj + bias + residual (bf16, prefetch pipelined)
    bf16_gemm_full<3><<<dim3(NPIX / BN, CCH / BM, BATCH), 256>>>(
        w_proj, att, out, b_proj, x, nullptr, nullptr,
        CCH, NPIX, CCH, CCH, NPIX);
}

// round 16
// speedup vs baseline: 1.0812x; 1.0212x over previous
#include <cuda_runtime.h>
#include <cuda_bf16.h>
#include <cstdint>

#define BATCH   16
#define CCH     512
#define NPIX    1024          // 32*32
#define HEADS   4
#define HD      128           // CCH / HEADS
#define GROUPS  32
#define CPG     (CCH / GROUPS)   // 16
#define GEPS    1e-5f
#define ATT_SCALE 0.088388347648318447f   // 128^-0.5
#define NBH     (BATCH * HEADS)           // 64

// ---------------- scratch (device globals; no allocations allowed) ----------
__device__ float g_att[BATCH * CCH * NPIX];                 // 33.5 MB fp32
__device__ float g_gnmu [BATCH * GROUPS];
__device__ float g_gninv[BATCH * GROUPS];
__device__ __nv_bfloat16 g_qc[(size_t)BATCH * CCH * NPIX];  // [b][c][q], scaled
__device__ __nv_bfloat16 g_kc[(size_t)BATCH * CCH * NPIX];  // [b][c][q]
__device__ __nv_bfloat16 g_vb[(size_t)BATCH * CCH * NPIX];  // [b][c][key]
__device__ __nv_bfloat16 g_qT[(size_t)NBH * NPIX * HD];     // [bh][q][c]
__device__ __nv_bfloat16 g_kT[(size_t)NBH * NPIX * HD];     // [bh][key][c]

__device__ __forceinline__ uint32_t pack_bf2(float a, float b) {
    __nv_bfloat162 h = __floats2bfloat162_rn(a, b);
    return *(uint32_t*)&h;
}

// ---------------- GroupNorm stats only ---------------------------------------
__global__ void gn_stats(const float* __restrict__ x) {
    const int bg = blockIdx.x;
    const int b  = bg / GROUPS;
    const int g  = bg % GROUPS;
    const int M  = CPG * NPIX;                  // 16384
    const float* xp = x + ((size_t)b * CCH + (size_t)g * CPG) * NPIX;

    float s = 0.f, ss = 0.f;
    for (int i = threadIdx.x; i < M; i += blockDim.x) {
        float v = xp[i];
        s += v; ss += v * v;
    }
    __shared__ float red[64];
    #pragma unroll
    for (int o = 16; o; o >>= 1) {
        s  += __shfl_xor_sync(0xffffffffu, s,  o);
        ss += __shfl_xor_sync(0xffffffffu, ss, o);
    }
    const int warp = threadIdx.x >> 5, lane = threadIdx.x & 31;
    if (lane == 0) { red[warp] = s; red[warp + 32] = ss; }
    __syncthreads();
    if (threadIdx.x == 0) {
        float s2 = 0.f, ss2 = 0.f;
        #pragma unroll
        for (int i = 0; i < 8; i++) { s2 += red[i]; ss2 += red[i + 32]; }
        float mu  = s2 / (float)M;
        float var = ss2 / (float)M - mu * mu;
        g_gnmu[bg]  = mu;
        g_gninv[bg] = rsqrtf(var + GEPS);
    }
}

// ---------------- bf16 MMA GEMM (R15 version, passing) ------------------------
#define BM 128
#define BN 128
#define BK 32
#define SW 20

#define MMA_BF16(c, a, b) \
    asm volatile("mma.sync.aligned.m16n8k16.row.col.f32.bf16.bf16.f32 " \
        "{%0,%1,%2,%3},{%4,%5,%6,%7},{%8,%9},{%0,%1,%2,%3};" \
        : "+f"((c)[0]), "+f"((c)[1]), "+f"((c)[2]), "+f"((c)[3]) \
        : "r"((a)[0]), "r"((a)[1]), "r"((a)[2]), "r"((a)[3]), \
          "r"((b)[0]), "r"((b)[1]))

template<int MODE>
__global__ void __launch_bounds__(256, 2)
bf16_gemm_full(const float* __restrict__ Wg, const float* __restrict__ Xg,
               float* __restrict__ Cg,
               const float* __restrict__ bias, const float* __restrict__ res,
               const float* __restrict__ gamma, const float* __restrict__ beta,
               int M, int N, int K, int lda, int ldb) {
    const int z  = blockIdx.z;
    const int m0 = blockIdx.y * BM;
    const int n0 = blockIdx.x * BN;
    const size_t Boff = (size_t)z * CCH * NPIX;

    __shared__ uint32_t As[BM * SW];
    __shared__ uint32_t Bs[BN * SW];
    __shared__ float s_mu[GROUPS], s_inv[GROUPS];
    __shared__ float s_gam[CCH], s_bet[CCH];

    const int tid  = threadIdx.x;
    const int lane = tid & 31;
    const int warp = tid >> 5;
    const int g = lane >> 2, t = lane & 3;
    const int wm0 = (warp >> 2) * 64;
    const int wn0 = (warp & 3) * 32;

    if (MODE == 0) {
        if (tid < GROUPS) {
            s_mu[tid]  = g_gnmu[z * GROUPS + tid];
            s_inv[tid] = g_gninv[z * GROUPS + tid];
        }
        for (int i = tid; i < CCH; i += 256) {
            s_gam[i] = gamma[i];
            s_bet[i] = beta[i];
        }
        __syncthreads();
    }

    float cfr[4][4][4];
    #pragma unroll
    for (int i = 0; i < 4; i++)
        #pragma unroll
        for (int j = 0; j < 4; j++)
            #pragma unroll
            for (int q = 0; q < 4; q++) cfr[i][j][q] = 0.f;

    const int amr = tid >> 1;
    const int akw = (tid & 1) * 8;
    const int bkp = tid >> 5;
    const int bln = tid & 31;

    float4 ar[4];
    float  br[2][2][4];

    {   // preload kt = 0
        const float* ap = Wg + (size_t)(m0 + amr) * lda + akw * 2;
        #pragma unroll
        for (int i = 0; i < 4; i++) ar[i] = *(const float4*)(ap + i * 4);
        #pragma unroll
        for (int half = 0; half < 2; half++) {
            int kp = bkp + half * 8;
            const float* r0 = Xg + Boff + (size_t)(2 * kp) * ldb + n0;
            const float* r1 = r0 + ldb;
            #pragma unroll
            for (int c = 0; c < 4; c++) {
                int n = bln + 32 * c;
                br[half][0][c] = r0[n];
                br[half][1][c] = r1[n];
            }
        }
    }

    for (int kt = 0; kt < K; kt += BK) {
        __syncthreads();
        {
            uint32_t buf[8];
            #pragma unroll
            for (int i = 0; i < 4; i++) {
                buf[i * 2 + 0] = pack_bf2(ar[i].x, ar[i].y);
                buf[i * 2 + 1] = pack_bf2(ar[i].z, ar[i].w);
            }
            uint32_t* dst = As + amr * SW + akw;
            *(uint4*)(dst)     = *(uint4*)(buf);
            *(uint4*)(dst + 4) = *(uint4*)(buf + 4);
        }
        {
            #pragma unroll
            for (int half = 0; half < 2; half++) {
                int kp = bkp + half * 8;
                int ch = kt + 2 * kp;
                float a0 = 1.f, c0 = 0.f, a1 = 1.f, c1 = 0.f;
                if (MODE == 0) {
                    float i0 = s_inv[ch >> 4],       m0v = s_mu[ch >> 4];
                    float i1 = s_inv[(ch + 1) >> 4], m1v = s_mu[(ch + 1) >> 4];
                    a0 = i0 * s_gam[ch];     c0 = s_bet[ch]     - m0v * a0;
                    a1 = i1 * s_gam[ch + 1]; c1 = s_bet[ch + 1] - m1v * a1;
                }
                #pragma unroll
                for (int c = 0; c < 4; c++) {
                    int n = bln + 32 * c;
                    float v0 = br[half][0][c], v1 = br[half][1][c];
                    if (MODE == 0) { v0 = v0 * a0 + c0; v1 = v1 * a1 + c1; }
                    Bs[n * SW + kp] = pack_bf2(v0, v1);
                }
            }
        }
        __syncthreads();

        if (kt + BK < K) {
            const float* ap = Wg + (size_t)(m0 + amr) * lda + (kt + BK) + akw * 2;
            #pragma unroll
            for (int i = 0; i < 4; i++) ar[i] = *(const float4*)(ap + i * 4);
            #pragma unroll
            for (int half = 0; half < 2; half++) {
                int kp = bkp + half * 8;
                const float* r0 = Xg + Boff + (size_t)(kt + BK + 2 * kp) * ldb + n0;
                const float* r1 = r0 + ldb;
                #pragma unroll
                for (int c = 0; c < 4; c++) {
                    int n = bln + 32 * c;
                    br[half][0][c] = r0[n];
                    br[half][1][c] = r1[n];
                }
            }
        }

        #pragma unroll
        for (int kk = 0; kk < 2; kk++) {
            const int wb = kk * 8;
            uint32_t af[4][4], bf[4][2];
            #pragma unroll
            for (int mi = 0; mi < 4; mi++) {
                const uint32_t* p = As + (wm0 + mi * 16 + g) * SW + wb + t;
                af[mi][0] = p[0];
                af[mi][1] = p[8 * SW];
                af[mi][2] = p[4];
                af[mi][3] = p[8 * SW + 4];
            }
            #pragma unroll
            for (int ni = 0; ni < 4; ni++) {
                const uint32_t* p = Bs + (wn0 + ni * 8 + g) * SW + wb + t;
                bf[ni][0] = p[0];
                bf[ni][1] = p[4];
            }
            #pragma unroll
            for (int mi = 0; mi < 4; mi++)
                #pragma unroll
                for (int ni = 0; ni < 4; ni++)
                    MMA_BF16(cfr[mi][ni], af[mi], bf[ni]);
        }
    }

    #pragma unroll
    for (int mi = 0; mi < 4; mi++) {
        #pragma unroll
        for (int rr = 0; rr < 2; rr++) {
            int grow = m0 + wm0 + mi * 16 + g + rr * 8;
            float bv = bias[grow];
            if (MODE == 0) {
                int sect = grow >> 9;
                int ch   = grow & 511;
                float sc = (sect == 0) ? ATT_SCALE : 1.f;
                __nv_bfloat16* dst = (sect == 0) ? g_qc
                                   : (sect == 1) ? g_kc : g_vb;
                size_t base = ((size_t)z * CCH + ch) * NPIX;
                #pragma unroll
                for (int ni = 0; ni < 4; ni++) {
                    int gcol = n0 + wn0 + ni * 8 + 2 * t;
                    float v0 = (cfr[mi][ni][rr * 2 + 0] + bv) * sc;
                    float v1 = (cfr[mi][ni][rr * 2 + 1] + bv) * sc;
                    *(uint32_t*)(dst + base + gcol) = pack_bf2(v0, v1);
                }
            } else {
                #pragma unroll
                for (int ni = 0; ni < 4; ni++) {
                    int gcol = n0 + wn0 + ni * 8 + 2 * t;
                    size_t idx = (size_t)z * CCH * NPIX + (size_t)grow * N + gcol;
                    Cg[idx]     = cfr[mi][ni][rr * 2 + 0] + bv + res[idx];
                    Cg[idx + 1] = cfr[mi][ni][rr * 2 + 1] + bv + res[idx + 1];
                }
            }
        }
    }
}

// ---------------- prep: bf16 transpose Q,K to [bh][qk][c] --------------------
__global__ void prep_qkT() {
    __shared__ __nv_bfloat16 ts[32][33];
    const int z = blockIdx.z;
    const int bh = z >> 1, which = z & 1;
    const int b = bh >> 2, h = bh & 3;
    const int c0 = blockIdx.x * 32, q0 = blockIdx.y * 32;
    const __nv_bfloat16* src = (which == 0 ? g_qc : g_kc)
        + ((size_t)b * CCH + h * HD) * NPIX;
    __nv_bfloat16* dst = (which == 0 ? g_qT : g_kT) + (size_t)bh * NPIX * HD;

    #pragma unroll
    for (int i = 0; i < 4; i++) {
        int c = c0 + threadIdx.y + i * 8;
        ts[threadIdx.y + i * 8][threadIdx.x] = src[(size_t)c * NPIX + q0 + threadIdx.x];
    }
    __syncthreads();
    #pragma unroll
    for (int i = 0; i < 4; i++) {
        int q = q0 + threadIdx.y + i * 8;
        dst[(size_t)q * HD + c0 + threadIdx.x] = ts[threadIdx.x][threadIdx.y + i * 8];
    }
}

// ---------------- flash attention: 64-row CTA, 2 CTAs/SM ----------------------
#define LDW(p) (*(const uint32_t*)(p))
#define FSTR 136
#define QTILE_B (64 * FSTR * 2)         // 17408 bytes (64 query rows)
#define KVTILE_B (128 * FSTR * 2)       // 34816 bytes
#define QS_OFF  0
#define K_OFF   (QTILE_B)
#define V_OFF   (QTILE_B + KVTILE_B)
#define FLASH_SMEM (QTILE_B + 2 * KVTILE_B + 128)   // 87168 B -> 2 CTAs/SM

__global__ void __launch_bounds__(128, 2) flash_kernel() {
    extern __shared__ char smbuf[];
    __nv_bfloat16* Qs = (__nv_bfloat16*)(smbuf + QS_OFF);
    __nv_bfloat16* Ks = (__nv_bfloat16*)(smbuf + K_OFF);
    __nv_bfloat16* Vs = (__nv_bfloat16*)(smbuf + V_OFF);
    float* Ot = (float*)(smbuf + K_OFF);   // reused after mainloop: 128*132*4=67.6KB <= 69.6KB

    const int tid = threadIdx.x, lane = tid & 31, warp = tid >> 5;  // 4 warps
    const int g = lane >> 2, t = lane & 3;
    const int wm = warp * 16;               // 16 query rows per warp (64 total)
    const int bh = blockIdx.y, b = bh >> 2, h = bh & 3;
    const int q0 = blockIdx.x * 64;         // 64-row query tile

    const __nv_bfloat16* qsrc = g_qT + (size_t)bh * NPIX * HD + (size_t)q0 * HD;
    const __nv_bfloat16* ksrc = g_kT + (size_t)bh * NPIX * HD;
    const __nv_bfloat16* vsrc = g_vb + ((size_t)b * CCH + h * HD) * NPIX;

    // stage Q: 64 rows x 128 c = 1024 uint4-transfers / 128 threads = 8 its
    #pragma unroll
    for (int it = 0; it < 8; it++) {
        int idx = tid + it * 128;
        int row = idx >> 4, col8 = (idx & 15) * 8;
        *(uint4*)(Qs + row * FSTR + col8) = *(const uint4*)(qsrc + row * HD + col8);
    }

    float oacc[16][4];
    #pragma unroll
    for (int nj = 0; nj < 16; nj++)
        #pragma unroll
        for (int q = 0; q < 4; q++) oacc[nj][q] = 0.f;
    float m_run[2] = { -1e30f, -1e30f }, l_run[2] = { 0.f, 0.f };

    for (int kc = 0; kc < 8; kc++) {
        __syncthreads();
        // stage K/V chunk: 128 rows x 16 col8-groups = 2048 / 128 threads = 16 its
        #pragma unroll
        for (int it = 0; it < 16; it++) {
            int idx = tid + it * 128;
            int row = idx >> 4, col8 = (idx & 15) * 8;
            *(uint4*)(Ks + row * FSTR + col8) =
                *(const uint4*)(ksrc + (size_t)(kc * 128 + row) * HD + col8);
            *(uint4*)(Vs + row * FSTR + col8) =
                *(const uint4*)(vsrc + (size_t)row * NPIX + kc * 128 + col8);
        }
        __syncthreads();

        // ---- S = Q K^T ----
        float sacc[16][4];
        #pragma unroll
        for (int ni = 0; ni < 16; ni++)
            #pragma unroll
            for (int q = 0; q < 4; q++) sacc[ni][q] = 0.f;
        #pragma unroll
        for (int ks = 0; ks < 8; ks++) {
            const int kb = ks * 16;
            uint32_t af[4];
            const __nv_bfloat16* pq = Qs + (wm + g) * FSTR + kb + 2 * t;
            af[0] = LDW(pq);
            af[1] = LDW(pq + 8 * FSTR);
            af[2] = LDW(pq + 8);
            af[3] = LDW(pq + 8 * FSTR + 8);
            #pragma unroll
            for (int ni = 0; ni < 16; ni++) {
                uint32_t bf[2];
                const __nv_bfloat16* pk = Ks + (ni * 8 + g) * FSTR + kb + 2 * t;
                bf[0] = LDW(pk);
                bf[1] = LDW(pk + 8);
                MMA_BF16(sacc[ni], af, bf);
            }
        }

        // ---- online softmax (warp-local) ----
        float mnew[2], al[2];
        #pragma unroll
        for (int rr = 0; rr < 2; rr++) {
            float mx = -1e30f;
            #pragma unroll
            for (int ni = 0; ni < 16; ni++)
                mx = fmaxf(mx, fmaxf(sacc[ni][2 * rr], sacc[ni][2 * rr + 1]));
            mx = fmaxf(mx, __shfl_xor_sync(0xffffffffu, mx, 1));
            mx = fmaxf(mx, __shfl_xor_sync(0xffffffffu, mx, 2));
            float mn = fmaxf(m_run[rr], mx);
            al[rr] = __expf(m_run[rr] - mn);
            mnew[rr] = mn;
        }
        uint32_t pp[16][2];
        float lloc[2] = { 0.f, 0.f };
        #pragma unroll
        for (int ni = 0; ni < 16; ni++) {
            float p0 = __expf(sacc[ni][0] - mnew[0]);
            float p1 = __expf(sacc[ni][1] - mnew[0]);
            float p2 = __expf(sacc[ni][2] - mnew[1]);
            float p3 = __expf(sacc[ni][3] - mnew[1]);
            lloc[0] += p0 + p1;
            lloc[1] += p2 + p3;
            pp[ni][0] = pack_bf2(p0, p1);
            pp[ni][1] = pack_bf2(p2, p3);
        }
        #pragma unroll
        for (int rr = 0; rr < 2; rr++) {
            float s = lloc[rr];
            s += __shfl_xor_sync(0xffffffffu, s, 1);
            s += __shfl_xor_sync(0xffffffffu, s, 2);
            l_run[rr] = l_run[rr] * al[rr] + s;
            m_run[rr] = mnew[rr];
        }
        #pragma unroll
        for (int nj = 0; nj < 16; nj++) {
            oacc[nj][0] *= al[0]; oacc[nj][1] *= al[0];
            oacc[nj][2] *= al[1]; oacc[nj][3] *= al[1];
        }

        // ---- O += P V^T (register P) ----
        #pragma unroll
        for (int ks = 0; ks < 8; ks++) {
            uint32_t af[4] = { pp[2 * ks][0], pp[2 * ks][1],
                               pp[2 * ks + 1][0], pp[2 * ks + 1][1] };
            const int kb = ks * 16;
            #pragma unroll
            for (int nj = 0; nj < 16; nj++) {
                uint32_t bf[2];
                const __nv_bfloat16* pv = Vs + (nj * 8 + g) * FSTR + kb + 2 * t;
                bf[0] = LDW(pv);
                bf[1] = LDW(pv + 8);
                MMA_BF16(oacc[nj], af, bf);
            }
        }
    }

    // ---- epilogue: smem transpose -> coalesced [c][q] store ----
    __syncthreads();
    float inv0 = 1.f / l_run[0], inv1 = 1.f / l_run[1];
    #pragma unroll
    for (int nj = 0; nj < 16; nj++)
        #pragma unroll
        for (int q = 0; q < 4; q++) {
            int col = nj * 8 + 2 * t + (q & 1);              // c: 0..127
            int row = wm + g + 8 * (q >> 1);                 // q: 0..63
            Ot[col * 132 + row] = oacc[nj][q] * ((q >> 1) ? inv1 : inv0);
        }
    __syncthreads();
    float* og = g_att + ((size_t)b * CCH + h * HD) * NPIX + q0;
    // store: 128 c x 16 q4-groups(64 q) = 2048 float4 / 128 threads = 16 its
    #pragma unroll
    for (int it = 0; it < 16; it++) {
        int idx = tid + it * 128;
        int c = idx >> 4, q4 = (idx & 15) << 2;
        *(float4*)(og + (size_t)c * NPIX + q4) = *(const float4*)(Ot + c * 132 + q4);
    }
}

// ---------------- launch -----------------------------------------------------
extern "C" void kernel_launch(void* const* d_in, const int* in_sizes, int n_in,
                              void* d_out, int out_size) {
    const float* x      = (const float*)d_in[0];
    const float* gamma  = (const float*)d_in[1];
    const float* beta   = (const float*)d_in[2];
    const float* w_qkv  = (const float*)d_in[3];
    const float* b_qkv  = (const float*)d_in[4];
    const float* w_proj = (const float*)d_in[5];
    const float* b_proj = (const float*)d_in[6];
    float* out = (float*)d_out;

    float* att;
    cudaGetSymbolAddress((void**)&att, g_att);

    cudaFuncSetAttribute(flash_kernel,
        cudaFuncAttributeMaxDynamicSharedMemorySize, FLASH_SMEM);

    // 1) GroupNorm statistics
    gn_stats<<<BATCH * GROUPS, 256>>>(x);

    // 2) QKV projection (bf16, GN fused, prefetch pipelined)
    bf16_gemm_full<0><<<dim3(NPIX / BN, 3 * CCH / BM, BATCH), 256>>>(
        w_qkv, x, nullptr, b_qkv, nullptr, gamma, beta,
        3 * CCH, NPIX, CCH, CCH, NPIX);

    // 3) prep: Q/K bf16 transpose to [bh][q/key][c]
    prep_qkT<<<dim3(HD / 32, NPIX / 32, NBH * 2), dim3(32, 8)>>>();

    // 4) fused flash attention (64-row CTAs, 2 CTAs/SM)
    flash_kernel<<<dim3(NPIX / 64, NBH), 128, FLASH_SMEM>>>();

    // 5) proj + bias + residual (bf16, prefetch pipelined)
    bf16_gemm_full<3><<<dim3(NPIX / BN, CCH / BM, BATCH), 256>>>(
        w_proj, att, out, b_proj, x, nullptr, nullptr,
        CCH, NPIX, CCH, CCH, NPIX);
}